// round 1
// baseline (speedup 1.0000x reference)
#include <cuda_runtime.h>
#include <math.h>

#define NB 2
#define NC 256
#define NH 128
#define NW 512
#define KB 16
#define TM 64
#define NTHREADS 512
#define SMEM_BYTES (TM * NW * 4)   // 128 KB vol tile (aliases GEMM staging)

__global__ __launch_bounds__(NTHREADS, 1)
void cost_volume_kernel(const float* __restrict__ img1,
                        const float* __restrict__ img2,
                        const float* __restrict__ intri1,
                        const float* __restrict__ extri1,
                        const float* __restrict__ extri2,
                        float* __restrict__ out, int nout)
{
    extern __shared__ float smem[];
    float* A1s = smem;              // [KB][TM]    (4 KB)
    float* A2s = smem + KB * TM;    // [KB][NW]    (32 KB)
    float* vol = smem;              // [TM][NW]    (128 KB, aliases after GEMM)

    const int t    = threadIdx.x;
    const int cta  = blockIdx.x;          // b*NH*8 + h*8 + tile
    const int tile = cta & 7;
    const int bh   = cta >> 3;
    const int h    = bh & (NH - 1);
    const int b    = bh >> 7;
    const int w1_0 = tile * TM;

    const size_t cstride = (size_t)NH * NW;
    const float* g1 = img1 + ((size_t)b * NC * NH + h) * NW + w1_0;
    const float* g2 = img2 + ((size_t)b * NC * NH + h) * NW;

    const int tx = t & 63;   // w2 group
    const int ty = t >> 6;   // w1 group

    float acc[8][8];
    #pragma unroll
    for (int i = 0; i < 8; i++)
        #pragma unroll
        for (int j = 0; j < 8; j++) acc[i][j] = 0.f;

    for (int k0 = 0; k0 < NC; k0 += KB) {
        __syncthreads();
        // A1 chunk: KB*TM = 1024 floats, 2 per thread, coalesced along w1
        {
            int i = t;
            A1s[i] = g1[(size_t)(k0 + (i >> 6)) * cstride + (i & 63)];
            i = t + NTHREADS;
            A1s[i] = g1[(size_t)(k0 + (i >> 6)) * cstride + (i & 63)];
        }
        // A2 chunk: KB*NW = 8192 floats = 2048 float4, 4 per thread
        #pragma unroll
        for (int v = 0; v < 4; v++) {
            int i = v * NTHREADS + t;
            int c = i >> 7;
            int w = (i & 127) << 2;
            *(float4*)(A2s + c * NW + w) =
                *(const float4*)(g2 + (size_t)(k0 + c) * cstride + w);
        }
        __syncthreads();
        #pragma unroll
        for (int k = 0; k < KB; k++) {
            // 4+4 split keeps LDS.128 lane stride at 16B -> conflict-free
            float4 a0 = *(float4*)(A1s + k * TM + ty * 4);
            float4 a1 = *(float4*)(A1s + k * TM + 32 + ty * 4);
            float4 b0 = *(float4*)(A2s + k * NW + tx * 4);
            float4 b1 = *(float4*)(A2s + k * NW + 256 + tx * 4);
            float av[8] = {a0.x, a0.y, a0.z, a0.w, a1.x, a1.y, a1.z, a1.w};
            float bv[8] = {b0.x, b0.y, b0.z, b0.w, b1.x, b1.y, b1.z, b1.w};
            #pragma unroll
            for (int i = 0; i < 8; i++)
                #pragma unroll
                for (int j = 0; j < 8; j++)
                    acc[i][j] += av[i] * bv[j];
        }
    }

    __syncthreads();   // done reading A1s/A2s; safe to alias vol over them
    const float scale = 0.0625f;   // 1/sqrt(C)
    #pragma unroll
    for (int i = 0; i < 8; i++) {
        int r = (i < 4) ? (ty * 4 + i) : (32 + ty * 4 + (i - 4));
        float4 v0 = make_float4(acc[i][0] * scale, acc[i][1] * scale,
                                acc[i][2] * scale, acc[i][3] * scale);
        float4 v1 = make_float4(acc[i][4] * scale, acc[i][5] * scale,
                                acc[i][6] * scale, acc[i][7] * scale);
        *(float4*)(vol + r * NW + tx * 4)       = v0;
        *(float4*)(vol + r * NW + 256 + tx * 4) = v1;
    }
    __syncthreads();

    // per-batch fx * baseline
    float fx = intri1[b * 9];
    float dx = extri1[b * 16 + 3]  - extri2[b * 16 + 3];
    float dy = extri1[b * 16 + 7]  - extri2[b * 16 + 7];
    float dz = extri1[b * 16 + 11] - extri2[b * 16 + 11];
    float fb = fx * sqrtf(dx * dx + dy * dy + dz * dz);

    const int warp = t >> 5, lane = t & 31;
    #pragma unroll
    for (int rr = 0; rr < 4; rr++) {
        int r = warp * 4 + rr;
        int w1g = w1_0 + r;
        const float* row = vol + r * NW;

        float m = -INFINITY;
        for (int i = lane; i < NW; i += 32) m = fmaxf(m, row[i]);
        #pragma unroll
        for (int off = 16; off; off >>= 1)
            m = fmaxf(m, __shfl_xor_sync(0xffffffffu, m, off));

        float Z = 0.f, S = 0.f, Mm = 0.f;
        for (int i = lane; i < NW; i += 32) {
            float e = __expf(row[i] - m);
            Z += e;                                 // softmax denom over ALL w2
            if (i <= w1g) {                          // tril mask applied AFTER softmax
                S  += e * (float)i;
                Mm  = fmaxf(Mm, e);
            }
        }
        #pragma unroll
        for (int off = 16; off; off >>= 1) {
            Z += __shfl_xor_sync(0xffffffffu, Z, off);
            S += __shfl_xor_sync(0xffffffffu, S, off);
            Mm = fmaxf(Mm, __shfl_xor_sync(0xffffffffu, Mm, off));
        }

        if (lane == 0) {
            float inv     = 1.f / Z;
            float corresp = S * inv;
            float conf    = Mm * inv;
            float disp    = fabsf(corresp - (float)w1g) * (1.0f / NW);
            disp          = fmaxf(disp, 0.1f);
            float depth   = fb / disp;
            int oidx = (b * NH + h) * NW + w1g;
            out[oidx]        = depth;
            out[nout + oidx] = conf;
        }
    }
}

extern "C" void kernel_launch(void* const* d_in, const int* in_sizes, int n_in,
                              void* d_out, int out_size) {
    const float* img1   = (const float*)d_in[0];
    const float* img2   = (const float*)d_in[1];
    const float* intri1 = (const float*)d_in[2];
    const float* extri1 = (const float*)d_in[4];
    const float* extri2 = (const float*)d_in[5];
    float* out = (float*)d_out;
    int nout = out_size / 2;   // depth block, then confidence block

    cudaFuncSetAttribute(cost_volume_kernel,
                         cudaFuncAttributeMaxDynamicSharedMemorySize, SMEM_BYTES);
    dim3 grid(NB * NH * (NW / TM));   // 2048 CTAs
    cost_volume_kernel<<<grid, NTHREADS, SMEM_BYTES>>>(
        img1, img2, intri1, extri1, extri2, out, nout);
}

// round 3
// speedup vs baseline: 2.3338x; 2.3338x over previous
#include <cuda_runtime.h>
#include <cuda_bf16.h>
#include <cstdint>
#include <math.h>

#define NB 2
#define NC 256
#define NH 128
#define NW 512
#define KC 16
#define NCHUNK (NC / KC)      // 16
#define TM 64                 // w1 rows per CTA
#define NTHREADS 512
#define ROWB 48               // padded smem row stride (32B data + 16B pad)

#define AH_OFF 0
#define AL_OFF (TM * ROWB)               // 3072
#define BH_OFF (2 * TM * ROWB)           // 6144
#define BL_OFF (BH_OFF + NW * ROWB)      // 30720
#define BUFB   (BL_OFF + NW * ROWB)      // 55296
#define PART_OFF (2 * BUFB)              // 110592
#define SMEM_BYTES (PART_OFF + TM * 4 * 3 * 4)   // 113664

static __device__ __forceinline__ uint32_t s2u(const void* p) {
    uint32_t a;
    asm("{ .reg .u64 t; cvta.to.shared.u64 t, %1; cvt.u32.u64 %0, t; }" : "=r"(a) : "l"(p));
    return a;
}

#define LDSM4(r, addr) \
    asm volatile("ldmatrix.sync.aligned.m8n8.x4.shared.b16 {%0,%1,%2,%3}, [%4];" \
        : "=r"((r)[0]), "=r"((r)[1]), "=r"((r)[2]), "=r"((r)[3]) : "r"(addr))

#define MMA(acc, a, b0, b1) \
    asm volatile("mma.sync.aligned.m16n8k16.row.col.f32.bf16.bf16.f32 " \
        "{%0,%1,%2,%3}, {%4,%5,%6,%7}, {%8,%9}, {%0,%1,%2,%3};" \
        : "+f"((acc)[0]), "+f"((acc)[1]), "+f"((acc)[2]), "+f"((acc)[3]) \
        : "r"((a)[0]), "r"((a)[1]), "r"((a)[2]), "r"((a)[3]), "r"(b0), "r"(b1))

// fp32 -> (hi = truncated bf16, lo = rn-bf16 of exact residual)
static __device__ __forceinline__ void cvt_pair(float f0, float f1,
                                                uint32_t& hw, uint32_t& lw) {
    uint32_t u0 = __float_as_uint(f0), u1 = __float_as_uint(f1);
    hw = __byte_perm(u0, u1, 0x7632);
    float l0 = f0 - __uint_as_float(u0 & 0xFFFF0000u);
    float l1 = f1 - __uint_as_float(u1 & 0xFFFF0000u);
    __nv_bfloat162 p = __floats2bfloat162_rn(l0, l1);
    lw = *(uint32_t*)&p;
}

__global__ __launch_bounds__(NTHREADS, 1)
void cost_volume_mma(const float* __restrict__ img1, const float* __restrict__ img2,
                     const float* __restrict__ intri1, const float* __restrict__ extri1,
                     const float* __restrict__ extri2, float* __restrict__ out, int nout)
{
    extern __shared__ char smem[];
    const uint32_t smem_u = s2u(smem);
    const int t = threadIdx.x;
    const int lane = t & 31, wid = t >> 5;
    const int wm = wid >> 2, wn = wid & 3;     // 4x4 warp grid: m-band 16, n-slice 128

    const int cta = blockIdx.x;                // bh*8 + tile (tiles of same bh adjacent)
    const int tile = cta & 7;
    const int bh = cta >> 3;
    const int h = bh & (NH - 1);
    const int b = bh >> 7;
    const int w1_0 = tile * TM;

    const size_t cstr = (size_t)NH * NW;
    const float* g1 = img1 + ((size_t)b * NC * NH + h) * NW + w1_0;
    const float* g2 = img2 + ((size_t)b * NC * NH + h) * NW;

    // A-load assignment: row = t&63, channel pair = 2*(t>>6)
    const int ar = t & 63, ac = (t >> 6) * 2;
    const float* srcA = g1 + ar;
    const float* srcB = g2 + t;                // B row = w2 = t

    float acc[64];
    #pragma unroll
    for (int i = 0; i < 64; i++) acc[i] = 0.f;

    float stB[KC], stA[2];

    // ---- prologue: chunk 0 ----
    #pragma unroll
    for (int j = 0; j < KC; j++) stB[j] = __ldg(srcB + (size_t)j * cstr);
    stA[0] = __ldg(srcA + (size_t)ac * cstr);
    stA[1] = __ldg(srcA + (size_t)(ac + 1) * cstr);
    {
        char* bb = smem;
        uint32_t hw[8], lw[8];
        #pragma unroll
        for (int j = 0; j < 8; j++) cvt_pair(stB[2*j], stB[2*j+1], hw[j], lw[j]);
        *(uint4*)(bb + BH_OFF + t * ROWB)      = make_uint4(hw[0], hw[1], hw[2], hw[3]);
        *(uint4*)(bb + BH_OFF + t * ROWB + 16) = make_uint4(hw[4], hw[5], hw[6], hw[7]);
        *(uint4*)(bb + BL_OFF + t * ROWB)      = make_uint4(lw[0], lw[1], lw[2], lw[3]);
        *(uint4*)(bb + BL_OFF + t * ROWB + 16) = make_uint4(lw[4], lw[5], lw[6], lw[7]);
        uint32_t ahw, alw;
        cvt_pair(stA[0], stA[1], ahw, alw);
        *(uint32_t*)(bb + AH_OFF + ar * ROWB + ac * 2) = ahw;
        *(uint32_t*)(bb + AL_OFF + ar * ROWB + ac * 2) = alw;
    }
    __syncthreads();

    const uint32_t aoff = (uint32_t)(wm * 16 + (lane & 15)) * ROWB + (lane >> 4) * 16;
    const uint32_t boff = (uint32_t)(wn * 128 + (lane & 15)) * ROWB + (lane >> 4) * 16;

    for (int chunk = 0; chunk < NCHUNK; chunk++) {
        // issue next chunk's global loads first (latency overlaps MMA below)
        if (chunk + 1 < NCHUNK) {
            const int k0 = (chunk + 1) * KC;
            #pragma unroll
            for (int j = 0; j < KC; j++) stB[j] = __ldg(srcB + (size_t)(k0 + j) * cstr);
            stA[0] = __ldg(srcA + (size_t)(k0 + ac) * cstr);
            stA[1] = __ldg(srcA + (size_t)(k0 + ac + 1) * cstr);
        }

        const uint32_t base = smem_u + (uint32_t)(chunk & 1) * BUFB;
        uint32_t Ah[4], Al[4];
        LDSM4(Ah, base + AH_OFF + aoff);
        LDSM4(Al, base + AL_OFF + aoff);
        #pragma unroll
        for (int nt = 0; nt < 8; nt++) {
            uint32_t Bh[4], Bl[4];
            LDSM4(Bh, base + BH_OFF + boff + nt * 16 * ROWB);
            LDSM4(Bl, base + BL_OFF + boff + nt * 16 * ROWB);
            float* a0 = acc + nt * 8;       // n-tile 2nt
            float* a1 = acc + nt * 8 + 4;   // n-tile 2nt+1
            MMA(a0, Ah, Bh[0], Bh[2]);
            MMA(a1, Ah, Bh[1], Bh[3]);
            MMA(a0, Ah, Bl[0], Bl[2]);
            MMA(a1, Ah, Bl[1], Bl[3]);
            MMA(a0, Al, Bh[0], Bh[2]);
            MMA(a1, Al, Bh[1], Bh[3]);
        }

        if (chunk + 1 < NCHUNK) {
            char* bb = smem + ((chunk + 1) & 1) * BUFB;
            uint32_t hw[8], lw[8];
            #pragma unroll
            for (int j = 0; j < 8; j++) cvt_pair(stB[2*j], stB[2*j+1], hw[j], lw[j]);
            *(uint4*)(bb + BH_OFF + t * ROWB)      = make_uint4(hw[0], hw[1], hw[2], hw[3]);
            *(uint4*)(bb + BH_OFF + t * ROWB + 16) = make_uint4(hw[4], hw[5], hw[6], hw[7]);
            *(uint4*)(bb + BL_OFF + t * ROWB)      = make_uint4(lw[0], lw[1], lw[2], lw[3]);
            *(uint4*)(bb + BL_OFF + t * ROWB + 16) = make_uint4(lw[4], lw[5], lw[6], lw[7]);
            uint32_t ahw, alw;
            cvt_pair(stA[0], stA[1], ahw, alw);
            *(uint32_t*)(bb + AH_OFF + ar * ROWB + ac * 2) = ahw;
            *(uint32_t*)(bb + AL_OFF + ar * ROWB + ac * 2) = alw;
        }
        __syncthreads();
    }

    // ---- epilogue: softmax stats straight from register accumulators ----
    const float scale = 0.0625f;   // 1/sqrt(256)
    const int r0 = wm * 16 + (lane >> 2);      // local rows r0, r0+8
    const int w1g0 = w1_0 + r0, w1g1 = w1g0 + 8;
    float Z0 = 0.f, S0 = 0.f, M0 = 0.f, Z1 = 0.f, S1 = 0.f, M1 = 0.f;
    #pragma unroll
    for (int nt = 0; nt < 16; nt++) {
        const int c0 = wn * 128 + nt * 8 + (lane & 3) * 2;
        float e;
        e = __expf(acc[nt*4+0] * scale); Z0 += e;
        if (c0     <= w1g0) { S0 += e * (float)c0;       M0 = fmaxf(M0, e); }
        e = __expf(acc[nt*4+1] * scale); Z0 += e;
        if (c0 + 1 <= w1g0) { S0 += e * (float)(c0 + 1); M0 = fmaxf(M0, e); }
        e = __expf(acc[nt*4+2] * scale); Z1 += e;
        if (c0     <= w1g1) { S1 += e * (float)c0;       M1 = fmaxf(M1, e); }
        e = __expf(acc[nt*4+3] * scale); Z1 += e;
        if (c0 + 1 <= w1g1) { S1 += e * (float)(c0 + 1); M1 = fmaxf(M1, e); }
    }
    #pragma unroll
    for (int off = 1; off <= 2; off <<= 1) {
        Z0 += __shfl_xor_sync(0xffffffffu, Z0, off);
        S0 += __shfl_xor_sync(0xffffffffu, S0, off);
        M0 = fmaxf(M0, __shfl_xor_sync(0xffffffffu, M0, off));
        Z1 += __shfl_xor_sync(0xffffffffu, Z1, off);
        S1 += __shfl_xor_sync(0xffffffffu, S1, off);
        M1 = fmaxf(M1, __shfl_xor_sync(0xffffffffu, M1, off));
    }
    float* part = (float*)(smem + PART_OFF);   // [64 rows][4 wn][3]
    if ((lane & 3) == 0) {
        int i0 = (r0 * 4 + wn) * 3, i1 = ((r0 + 8) * 4 + wn) * 3;
        part[i0] = Z0; part[i0+1] = S0; part[i0+2] = M0;
        part[i1] = Z1; part[i1+1] = S1; part[i1+2] = M1;
    }
    __syncthreads();

    if (t < TM) {
        float Zt = 0.f, St = 0.f, Mt = 0.f;
        #pragma unroll
        for (int g = 0; g < 4; g++) {
            const int q = (t * 4 + g) * 3;
            Zt += part[q]; St += part[q+1]; Mt = fmaxf(Mt, part[q+2]);
        }
        const float fx = __ldg(intri1 + b * 9);
        const float dx = __ldg(extri1 + b * 16 + 3)  - __ldg(extri2 + b * 16 + 3);
        const float dy = __ldg(extri1 + b * 16 + 7)  - __ldg(extri2 + b * 16 + 7);
        const float dz = __ldg(extri1 + b * 16 + 11) - __ldg(extri2 + b * 16 + 11);
        const float fb = fx * sqrtf(dx * dx + dy * dy + dz * dz);
        const float inv = 1.f / Zt;
        const float corresp = St * inv;
        const float conf = Mt * inv;
        float disp = fmaxf(fabsf(corresp - (float)(w1_0 + t)) * (1.0f / NW), 0.1f);
        const int oidx = (b * NH + h) * NW + w1_0 + t;
        out[oidx] = fb / disp;
        out[nout + oidx] = conf;
    }
}

extern "C" void kernel_launch(void* const* d_in, const int* in_sizes, int n_in,
                              void* d_out, int out_size) {
    const float* img1   = (const float*)d_in[0];
    const float* img2   = (const float*)d_in[1];
    const float* intri1 = (const float*)d_in[2];
    const float* extri1 = (const float*)d_in[4];
    const float* extri2 = (const float*)d_in[5];
    float* out = (float*)d_out;
    const int nout = out_size / 2;

    cudaFuncSetAttribute(cost_volume_mma,
                         cudaFuncAttributeMaxDynamicSharedMemorySize, SMEM_BYTES);
    dim3 grid(NB * NH * (NW / TM));   // 2048 CTAs
    cost_volume_mma<<<grid, NTHREADS, SMEM_BYTES>>>(
        img1, img2, intri1, extri1, extri2, out, nout);
}